// round 12
// baseline (speedup 1.0000x reference)
#include <cuda_runtime.h>
#include <cuda_fp16.h>
#include <cstdint>

// ---------------- problem constants ----------------
#define Bx      2
#define Tt      16
#define Hh      56
#define Ww      56
#define Cc      96
#define HEADS   3
#define HD      32
#define WT      8
#define WH      7
#define WWIN    7
#define STs     4
#define SHs     3
#define SWs     3
#define NTOK    392
#define NWIN    128
#define BWIN    256
#define LL      50176
#define TOK     100352
#define HIDDEN  384
#define SCALE   0.1767766952966369f

#define TBL_ROWSTRIDE 392
#define TBL_CLS_STRIDE 156800   // 400*392
#define AST 104                 // fp16 smem tile stride
#define SMEM_GEMM ((128 * AST + 96 * AST) * 2)   // 46592 B
#define SMEM_PROJ (128 * 100 * 4)                // 51200 B (proj: fp32 LN staging overlay)

// ---------------- scratch ----------------
__device__ __half g_q[BWIN * HEADS * NTOK * HD + 256];
__device__ __half g_k[BWIN * HEADS * NTOK * HD];
__device__ __half g_v[BWIN * HEADS * NTOK * HD];
__device__ __half g_owin[TOK * Cc];
__device__ float  g_x1[TOK * Cc];
__device__ __half g_h2[TOK * Cc];       // LN2(x1), fp16
__device__ __half g_m1[TOK * HIDDEN];
__device__ float  g_tbl[24 * TBL_CLS_STRIDE];

__device__ __forceinline__ int orig_index(int wloc, int n) {
    int wt = wloc >> 6;
    int wh = (wloc >> 3) & 7;
    int ww = wloc & 7;
    int it = n / 49;
    int r  = n % 49;
    int ih = r / 7;
    int iw = r % 7;
    int t = wt * WT + it;
    int h = wh * WH + ih;
    int w = ww * WWIN + iw;
    int to = (t + STs) & 15;
    int ho = h + SHs; if (ho >= Hh) ho -= Hh;
    int wo = w + SWs; if (wo >= Ww) wo -= Ww;
    return (to * Hh + ho) * Ww + wo;
}

__device__ __forceinline__ void cp16(void* dst, const void* src) {
    uint32_t d = (uint32_t)__cvta_generic_to_shared(dst);
    asm volatile("cp.async.cg.shared.global [%0], [%1], 16;" :: "r"(d), "l"(src));
}
__device__ __forceinline__ void cp_commit_wait() {
    asm volatile("cp.async.commit_group;");
    asm volatile("cp.async.wait_group 0;");
}
__device__ __forceinline__ uint32_t pack_h2(float lo, float hi) {
    __half2 h = __floats2half2_rn(lo, hi);
    return *(uint32_t*)&h;
}
__device__ __forceinline__ void mma_f16(float* c, const uint32_t* a, const uint32_t* b) {
    asm volatile(
        "mma.sync.aligned.m16n8k16.row.col.f32.f16.f16.f32 "
        "{%0,%1,%2,%3},{%4,%5,%6,%7},{%8,%9},{%0,%1,%2,%3};"
        : "+f"(c[0]), "+f"(c[1]), "+f"(c[2]), "+f"(c[3])
        : "r"(a[0]), "r"(a[1]), "r"(a[2]), "r"(a[3]), "r"(b[0]), "r"(b[1]));
}
__device__ __forceinline__ void mma_f16_k8(float* c, const uint32_t* a, uint32_t b) {
    asm volatile(
        "mma.sync.aligned.m16n8k8.row.col.f32.f16.f16.f32 "
        "{%0,%1,%2,%3},{%4,%5},{%6},{%0,%1,%2,%3};"
        : "+f"(c[0]), "+f"(c[1]), "+f"(c[2]), "+f"(c[3])
        : "r"(a[0]), "r"(a[1]), "r"(b));
}

// ---------------- bias+mask table ----------------
__global__ __launch_bounds__(256) void tbl_kernel(const float* __restrict__ rel_bias) {
    int q = blockIdx.x;
    int cls3 = blockIdx.y;
    int head = cls3 % 3, cls = cls3 / 3;
    int it1 = q / 49, r1 = q % 49, ih1 = r1 / 7, iw1 = r1 % 7;
    int bt = (cls >> 2) & 1, bh = (cls >> 1) & 1, bw = cls & 1;
    int rt1 = bt ? (it1 < 4 ? 1 : 2) : 0;
    int rh1 = bh ? (ih1 < 4 ? 1 : 2) : 0;
    int rw1 = bw ? (iw1 < 4 ? 1 : 2) : 0;
    float* dst = g_tbl + (size_t)cls3 * TBL_CLS_STRIDE + q * TBL_ROWSTRIDE;
    for (int k = threadIdx.x; k < NTOK; k += 256) {
        int it2 = k / 49, r2 = k % 49, ih2 = r2 / 7, iw2 = r2 % 7;
        float b = rel_bias[((it1 - it2 + 7) * 15 + (ih1 - ih2 + 6) * 13 + (iw1 - iw2 + 6)) * 3 + head];
        int rt2 = bt ? (it2 < 4 ? 1 : 2) : 0;
        int rh2 = bh ? (ih2 < 4 ? 1 : 2) : 0;
        int rw2 = bw ? (iw2 < 4 ? 1 : 2) : 0;
        if (rt1 != rt2 || rh1 != rh2 || rw1 != rw2) b -= 100.0f;
        dst[k] = b;
    }
}

// ---------------- unified fp16 GEMM: tile 128x96 ----------------
// EPI 0: qkv split+scale (A=x fp32, gather, LN1)
// EPI 1: proj + residual + fused LN2 -> g_x1 (fp32) + g_h2 (fp16), scattered
// EPI 2: fc1 (A=g_h2 fp16) + gelu -> g_m1
// EPI 3: fc2 (A=g_m1 fp16) + residual g_x1 -> Cout
template<int EPI, bool LN, bool GATHER, int KTOT>
__global__ __launch_bounds__(256, 2) void gemm_tc(const void* __restrict__ Ain,
                                                  const float* __restrict__ Bw,
                                                  const float* __restrict__ bias,
                                                  const float* __restrict__ gam,
                                                  const float* __restrict__ bet,
                                                  const float* __restrict__ res,
                                                  float* __restrict__ Cout) {
    extern __shared__ __half sm[];
    __half (*sA)[AST] = (__half(*)[AST])sm;
    __half (*sB)[AST] = (__half(*)[AST])(sm + 128 * AST);

    int m0 = blockIdx.y * 128;
    int n0 = blockIdx.x * 96;
    int tid = threadIdx.x;
    int lane = tid & 31, warp = tid >> 5;
    int wm = warp >> 1, wn = warp & 1;
    int g = lane >> 2, tig = lane & 3;

    float acc[2][6][4];
    #pragma unroll
    for (int i = 0; i < 2; i++)
        #pragma unroll
        for (int j = 0; j < 6; j++)
            #pragma unroll
            for (int c = 0; c < 4; c++) acc[i][j][c] = 0.0f;

    #pragma unroll 1
    for (int ch = 0; ch < KTOT / 96; ch++) {
        if (!LN) {  // A already fp16 in gmem
            const __half* Ah = (const __half*)Ain;
            for (int s = tid; s < 128 * 12; s += 256) {
                int row = s / 12, seg = s % 12;
                cp16(&sA[row][seg * 8], Ah + (size_t)(m0 + row) * KTOT + ch * 96 + seg * 8);
            }
        }
        // B tile (weights fp32 -> fp16)
        for (int s = tid; s < 96 * 24; s += 256) {
            int row = s / 24, f4 = s % 24;
            float4 v = __ldg((const float4*)(Bw + (size_t)(n0 + row) * KTOT + ch * 96) + f4);
            uint32_t* d = (uint32_t*)&sB[row][f4 * 4];
            d[0] = pack_h2(v.x, v.y);
            d[1] = pack_h2(v.z, v.w);
        }
        if (LN) {   // fp32 A rows -> registers -> LN -> fp16 smem (4 threads/row)
            int q4 = tid & 3, rr = tid >> 2;
            #pragma unroll
            for (int p = 0; p < 2; p++) {
                int row = p * 64 + rr;
                const float* src;
                if (GATHER) {
                    int m = m0 + row;
                    int w = m / NTOK, n = m % NTOK;
                    int b = w >> 7;
                    src = (const float*)Ain + ((size_t)b * LL + orig_index(w & 127, n)) * Cc + q4 * 24;
                } else {
                    src = (const float*)Ain + (size_t)(m0 + row) * 96 + q4 * 24;
                }
                float v[24];
                #pragma unroll
                for (int i = 0; i < 6; i++) *(float4*)&v[i * 4] = __ldg((const float4*)src + i);
                float s1 = 0.0f, s2 = 0.0f;
                #pragma unroll
                for (int i = 0; i < 24; i++) { s1 += v[i]; s2 += v[i] * v[i]; }
                s1 += __shfl_xor_sync(0xffffffffu, s1, 1);
                s1 += __shfl_xor_sync(0xffffffffu, s1, 2);
                s2 += __shfl_xor_sync(0xffffffffu, s2, 1);
                s2 += __shfl_xor_sync(0xffffffffu, s2, 2);
                float mean = s1 * (1.0f / 96.0f);
                float rstd = rsqrtf(s2 * (1.0f / 96.0f) - mean * mean + 1e-5f);
                #pragma unroll
                for (int i = 0; i < 12; i++) {
                    int c = q4 * 24 + 2 * i;
                    float a0 = (v[2 * i] - mean) * rstd * __ldg(gam + c) + __ldg(bet + c);
                    float a1 = (v[2 * i + 1] - mean) * rstd * __ldg(gam + c + 1) + __ldg(bet + c + 1);
                    *(uint32_t*)&sA[row][c] = pack_h2(a0, a1);
                }
            }
        } else {
            cp_commit_wait();
        }
        __syncthreads();

        #pragma unroll
        for (int ks = 0; ks < 6; ks++) {
            int kb = ks * 16;
            uint32_t a[2][4], b[6][2];
            #pragma unroll
            for (int i = 0; i < 2; i++) {
                int r = wm * 32 + i * 16 + g;
                a[i][0] = *(const uint32_t*)&sA[r][kb + 2 * tig];
                a[i][1] = *(const uint32_t*)&sA[r + 8][kb + 2 * tig];
                a[i][2] = *(const uint32_t*)&sA[r][kb + 2 * tig + 8];
                a[i][3] = *(const uint32_t*)&sA[r + 8][kb + 2 * tig + 8];
            }
            #pragma unroll
            for (int j = 0; j < 6; j++) {
                int n = wn * 48 + j * 8 + g;
                b[j][0] = *(const uint32_t*)&sB[n][kb + 2 * tig];
                b[j][1] = *(const uint32_t*)&sB[n][kb + 2 * tig + 8];
            }
            #pragma unroll
            for (int i = 0; i < 2; i++)
                #pragma unroll
                for (int j = 0; j < 6; j++) mma_f16(acc[i][j], a[i], b[j]);
        }
        __syncthreads();
    }

    if (EPI == 1) {
        // stage acc+bias into fp32 smem tile (full rows resident per block)
        float (*sX)[100] = (float(*)[100])sm;
        #pragma unroll
        for (int i = 0; i < 2; i++)
            #pragma unroll
            for (int j = 0; j < 6; j++)
                #pragma unroll
                for (int p = 0; p < 2; p++) {
                    int rl = wm * 32 + i * 16 + g + p * 8;
                    int col = wn * 48 + j * 8 + tig * 2;
                    sX[rl][col]     = acc[i][j][2 * p]     + bias[col];
                    sX[rl][col + 1] = acc[i][j][2 * p + 1] + bias[col + 1];
                }
        __syncthreads();
        // per-row: add residual, write x1 (fp32) + LN -> h2 (fp16), scattered
        int q4 = tid & 3, rr = tid >> 2;
        #pragma unroll
        for (int p2 = 0; p2 < 2; p2++) {
            int rl = p2 * 64 + rr;
            int m = m0 + rl;
            int w = m / NTOK, n = m % NTOK;
            int b2 = w >> 7;
            size_t tokbase = ((size_t)b2 * LL + orig_index(w & 127, n)) * Cc;
            float v[24];
            #pragma unroll
            for (int i = 0; i < 6; i++) {
                float4 r4 = __ldg((const float4*)(res + tokbase + q4 * 24) + i);
                v[i * 4 + 0] = sX[rl][q4 * 24 + i * 4 + 0] + r4.x;
                v[i * 4 + 1] = sX[rl][q4 * 24 + i * 4 + 1] + r4.y;
                v[i * 4 + 2] = sX[rl][q4 * 24 + i * 4 + 2] + r4.z;
                v[i * 4 + 3] = sX[rl][q4 * 24 + i * 4 + 3] + r4.w;
                *(float4*)(g_x1 + tokbase + q4 * 24 + i * 4) = *(float4*)&v[i * 4];
            }
            float s1 = 0.0f, s2 = 0.0f;
            #pragma unroll
            for (int i = 0; i < 24; i++) { s1 += v[i]; s2 += v[i] * v[i]; }
            s1 += __shfl_xor_sync(0xffffffffu, s1, 1);
            s1 += __shfl_xor_sync(0xffffffffu, s1, 2);
            s2 += __shfl_xor_sync(0xffffffffu, s2, 1);
            s2 += __shfl_xor_sync(0xffffffffu, s2, 2);
            float mean = s1 * (1.0f / 96.0f);
            float rstd = rsqrtf(s2 * (1.0f / 96.0f) - mean * mean + 1e-5f);
            #pragma unroll
            for (int i = 0; i < 12; i++) {
                int c = q4 * 24 + 2 * i;
                float a0 = (v[2 * i] - mean) * rstd * __ldg(gam + c) + __ldg(bet + c);
                float a1 = (v[2 * i + 1] - mean) * rstd * __ldg(gam + c + 1) + __ldg(bet + c + 1);
                *(uint32_t*)(g_h2 + tokbase + c) = pack_h2(a0, a1);
            }
        }
        return;
    }

    #pragma unroll
    for (int i = 0; i < 2; i++)
        #pragma unroll
        for (int j = 0; j < 6; j++)
            #pragma unroll
            for (int p = 0; p < 2; p++) {
                int m = m0 + wm * 32 + i * 16 + g + p * 8;
                int col = n0 + wn * 48 + j * 8 + tig * 2;
                float v0 = acc[i][j][2 * p] + bias[col];
                float v1 = acc[i][j][2 * p + 1] + bias[col + 1];
                if (EPI == 0) {
                    int w = m / NTOK, n = m % NTOK;
                    int part = col / 96;
                    int hh = col % 96;
                    int head = hh >> 5, d = hh & 31;
                    size_t dst = (((size_t)(w * 3 + head)) * NTOK + n) * HD + d;
                    if (part == 0)
                        *(__half2*)(g_q + dst) = __floats2half2_rn(v0 * SCALE, v1 * SCALE);
                    else if (part == 1)
                        *(__half2*)(g_k + dst) = __floats2half2_rn(v0, v1);
                    else
                        *(__half2*)(g_v + dst) = __floats2half2_rn(v0, v1);
                } else if (EPI == 2) {
                    float g0 = 0.5f * v0 * (1.0f + erff(v0 * 0.70710678118654752f));
                    float g1 = 0.5f * v1 * (1.0f + erff(v1 * 0.70710678118654752f));
                    *(__half2*)(g_m1 + (size_t)m * HIDDEN + col) = __floats2half2_rn(g0, g1);
                } else {
                    size_t dst = (size_t)m * Cc + col;
                    float2 x2 = *(const float2*)(g_x1 + dst);
                    float2 o2; o2.x = x2.x + v0; o2.y = x2.y + v1;
                    *(float2*)(Cout + dst) = o2;
                }
            }
}

// ---------------- fp16 MMA attention (32-key chunks, 3 blocks/SM) ----------------
#define SK_STR   40
#define SVT_STR  408
#define SMEM_ATTN ((392 * SK_STR + 32 * SVT_STR) * 2)   // 57472 B

__global__ __launch_bounds__(256, 3) void attn_mma_kernel() {
    extern __shared__ __half sm[];
    __half (*sK)[SK_STR] = (__half(*)[SK_STR])sm;
    __half* sVT = sm + 392 * SK_STR;

    int win  = blockIdx.x / HEADS;
    int head = blockIdx.x % HEADS;
    int tid  = threadIdx.x;
    int lane = tid & 31, warp = tid >> 5;
    int g = lane >> 2, tig = lane & 3;

    const __half* Kg = g_k + ((size_t)(win * HEADS + head)) * NTOK * HD;
    const __half* Vg = g_v + ((size_t)(win * HEADS + head)) * NTOK * HD;
    const __half* Qg = g_q + ((size_t)(win * HEADS + head)) * NTOK * HD;

    int wloc = win & 127;
    int wt = wloc >> 6, wh = (wloc >> 3) & 7, ww = wloc & 7;
    int cls = ((wt == 1) << 2) | ((wh == 7) << 1) | (ww == 7);
    const float* tbl = g_tbl + (size_t)(cls * 3 + head) * TBL_CLS_STRIDE;

    for (int i = tid; i < NTOK * 4; i += 256) {
        int row = i >> 2, seg = i & 3;
        uint4 kv = *(const uint4*)(Kg + row * HD + seg * 8);
        *(uint4*)&sK[row][seg * 8] = kv;
        uint4 vv = *(const uint4*)(Vg + row * HD + seg * 8);
        const __half2* pp = (const __half2*)&vv;
        int c = seg * 8;
        #pragma unroll
        for (int e = 0; e < 4; e++) {
            sVT[(c + 2 * e) * SVT_STR + row]     = __low2half(pp[e]);
            sVT[(c + 2 * e + 1) * SVT_STR + row] = __high2half(pp[e]);
        }
    }
    __syncthreads();

    for (int mt = warp; mt < 25; mt += 8) {
        int row0 = mt * 16 + g;
        const __half* Qr = Qg + row0 * HD;
        uint32_t aq[2][4];
        #pragma unroll
        for (int ks = 0; ks < 2; ks++) {
            aq[ks][0] = *(const uint32_t*)(Qr + ks * 16 + 2 * tig);
            aq[ks][1] = *(const uint32_t*)(Qr + 256 + ks * 16 + 2 * tig);
            aq[ks][2] = *(const uint32_t*)(Qr + ks * 16 + 2 * tig + 8);
            aq[ks][3] = *(const uint32_t*)(Qr + 256 + ks * 16 + 2 * tig + 8);
        }

        float o[4][4];
        #pragma unroll
        for (int nf = 0; nf < 4; nf++)
            #pragma unroll
            for (int e = 0; e < 4; e++) o[nf][e] = 0.0f;
        float sum0 = 0.0f, sum1 = 0.0f;

        #pragma unroll 1
        for (int c = 0; c < 12; c++) {            // 12 chunks of 32 keys
            int n0 = c * 32;
            float s[4][4];
            #pragma unroll
            for (int j = 0; j < 4; j++)
                #pragma unroll
                for (int e = 0; e < 4; e++) s[j][e] = 0.0f;
            #pragma unroll
            for (int ks = 0; ks < 2; ks++) {
                #pragma unroll
                for (int j = 0; j < 4; j++) {
                    const __half* kb = &sK[n0 + j * 8 + g][ks * 16 + 2 * tig];
                    uint32_t b[2];
                    b[0] = *(const uint32_t*)kb;
                    b[1] = *(const uint32_t*)(kb + 8);
                    mma_f16(s[j], aq[ks], b);
                }
            }
            #pragma unroll
            for (int j = 0; j < 4; j++) {
                int colBase = n0 + j * 8 + tig * 2;
                float2 t0 = *(const float2*)(tbl + (size_t)row0 * TBL_ROWSTRIDE + colBase);
                float2 t1 = *(const float2*)(tbl + (size_t)(row0 + 8) * TBL_ROWSTRIDE + colBase);
                s[j][0] = __expf(s[j][0] + t0.x);
                s[j][1] = __expf(s[j][1] + t0.y);
                s[j][2] = __expf(s[j][2] + t1.x);
                s[j][3] = __expf(s[j][3] + t1.y);
                sum0 += s[j][0] + s[j][1];
                sum1 += s[j][2] + s[j][3];
            }
            #pragma unroll
            for (int u = 0; u < 2; u++) {
                uint32_t ap[4];
                ap[0] = pack_h2(s[2 * u][0], s[2 * u][1]);
                ap[1] = pack_h2(s[2 * u][2], s[2 * u][3]);
                ap[2] = pack_h2(s[2 * u + 1][0], s[2 * u + 1][1]);
                ap[3] = pack_h2(s[2 * u + 1][2], s[2 * u + 1][3]);
                #pragma unroll
                for (int nf = 0; nf < 4; nf++) {
                    const __half* vb = sVT + (nf * 8 + g) * SVT_STR + n0 + u * 16 + 2 * tig;
                    uint32_t b[2];
                    b[0] = *(const uint32_t*)vb;
                    b[1] = *(const uint32_t*)(vb + 8);
                    mma_f16(o[nf], ap, b);
                }
            }
        }
        {   // tail: keys 384..391
            float t[4] = {0.0f, 0.0f, 0.0f, 0.0f};
            #pragma unroll
            for (int ks = 0; ks < 2; ks++) {
                const __half* kb = &sK[384 + g][ks * 16 + 2 * tig];
                uint32_t b[2];
                b[0] = *(const uint32_t*)kb;
                b[1] = *(const uint32_t*)(kb + 8);
                mma_f16(t, aq[ks], b);
            }
            int colBase = 384 + tig * 2;
            float2 t0 = *(const float2*)(tbl + (size_t)row0 * TBL_ROWSTRIDE + colBase);
            float2 t1 = *(const float2*)(tbl + (size_t)(row0 + 8) * TBL_ROWSTRIDE + colBase);
            t[0] = __expf(t[0] + t0.x);
            t[1] = __expf(t[1] + t0.y);
            t[2] = __expf(t[2] + t1.x);
            t[3] = __expf(t[3] + t1.y);
            sum0 += t[0] + t[1];
            sum1 += t[2] + t[3];
            uint32_t ap2[2];
            ap2[0] = pack_h2(t[0], t[1]);
            ap2[1] = pack_h2(t[2], t[3]);
            #pragma unroll
            for (int nf = 0; nf < 4; nf++) {
                uint32_t b0 = *(const uint32_t*)(sVT + (nf * 8 + g) * SVT_STR + 384 + 2 * tig);
                mma_f16_k8(o[nf], ap2, b0);
            }
        }

        sum0 += __shfl_xor_sync(0xffffffffu, sum0, 1);
        sum0 += __shfl_xor_sync(0xffffffffu, sum0, 2);
        sum1 += __shfl_xor_sync(0xffffffffu, sum1, 1);
        sum1 += __shfl_xor_sync(0xffffffffu, sum1, 2);
        float inv0 = 1.0f / sum0, inv1 = 1.0f / sum1;

        #pragma unroll
        for (int nf = 0; nf < 4; nf++) {
            int col = head * HD + nf * 8 + tig * 2;
            *(__half2*)(g_owin + ((size_t)(win * NTOK + row0)) * Cc + col) =
                __floats2half2_rn(o[nf][0] * inv0, o[nf][1] * inv0);
            if (row0 + 8 < NTOK)
                *(__half2*)(g_owin + ((size_t)(win * NTOK + row0 + 8)) * Cc + col) =
                    __floats2half2_rn(o[nf][2] * inv1, o[nf][3] * inv1);
        }
    }
}

// ---------------- launch ----------------
extern "C" void kernel_launch(void* const* d_in, const int* in_sizes, int n_in,
                              void* d_out, int out_size) {
    const float* x       = (const float*)d_in[0];
    const float* norm1_g = (const float*)d_in[1];
    const float* norm1_b = (const float*)d_in[2];
    const float* qkv_w   = (const float*)d_in[3];
    const float* qkv_b   = (const float*)d_in[4];
    const float* rel_b   = (const float*)d_in[5];
    const float* proj_w  = (const float*)d_in[6];
    const float* proj_b  = (const float*)d_in[7];
    const float* norm2_g = (const float*)d_in[8];
    const float* norm2_b = (const float*)d_in[9];
    const float* fc1_w   = (const float*)d_in[10];
    const float* fc1_b   = (const float*)d_in[11];
    const float* fc2_w   = (const float*)d_in[12];
    const float* fc2_b   = (const float*)d_in[13];
    float* out = (float*)d_out;

    void *owin, *h2, *m1;
    cudaGetSymbolAddress(&owin, g_owin);
    cudaGetSymbolAddress(&h2, g_h2);
    cudaGetSymbolAddress(&m1, g_m1);

    cudaFuncSetAttribute(attn_mma_kernel, cudaFuncAttributeMaxDynamicSharedMemorySize, SMEM_ATTN);
    cudaFuncSetAttribute(gemm_tc<0, true,  true,  96>,  cudaFuncAttributeMaxDynamicSharedMemorySize, SMEM_GEMM);
    cudaFuncSetAttribute(gemm_tc<1, false, false, 96>,  cudaFuncAttributeMaxDynamicSharedMemorySize, SMEM_PROJ);
    cudaFuncSetAttribute(gemm_tc<2, false, false, 96>,  cudaFuncAttributeMaxDynamicSharedMemorySize, SMEM_GEMM);
    cudaFuncSetAttribute(gemm_tc<3, false, false, 384>, cudaFuncAttributeMaxDynamicSharedMemorySize, SMEM_GEMM);

    // 0. bias+mask table
    tbl_kernel<<<dim3(392, 24), 256>>>(rel_b);
    // 1. QKV gemm (fused LN1 + roll/partition gather) -> fp16 q/k/v
    gemm_tc<0, true, true, 96><<<dim3(3, TOK / 128), 256, SMEM_GEMM>>>(
        x, qkv_w, qkv_b, norm1_g, norm1_b, nullptr, nullptr);
    // 2. attention (fp16 MMA) -> fp16 owin
    attn_mma_kernel<<<BWIN * HEADS, 256, SMEM_ATTN>>>();
    // 3. proj + residual + fused LN2 -> g_x1 (fp32) + g_h2 (fp16)
    gemm_tc<1, false, false, 96><<<dim3(1, TOK / 128), 256, SMEM_PROJ>>>(
        owin, proj_w, proj_b, norm2_g, norm2_b, x, nullptr);
    // 4. fc1 (A = fp16 g_h2) + gelu -> g_m1
    gemm_tc<2, false, false, 96><<<dim3(4, TOK / 128), 256, SMEM_GEMM>>>(
        h2, fc1_w, fc1_b, nullptr, nullptr, nullptr, (float*)m1);
    // 5. fc2 + residual -> fp32 out
    gemm_tc<3, false, false, 384><<<dim3(1, TOK / 128), 256, SMEM_GEMM>>>(
        m1, fc2_w, fc2_b, nullptr, nullptr, nullptr, out);
}